// round 8
// baseline (speedup 1.0000x reference)
#include <cuda_runtime.h>

// ReactDiffDynamics: per batch b (64), channels U,V of 512x512 fp32 (periodic):
//   dUdt = a*lap(U) + U - U^3 - k - V
//   dVdt = b*lap(V) + U - V
// lap = 5-point periodic stencil / dx^2, dx = 0.06451612903.
//
// R8: R7 geometry widened to 8 floats per thread in x (two float4s), RPT=4
// row-marching. Doubles independent loads in flight per thread (MLP_eff) to
// push achieved DRAM% past ~70% -- we are at the byte floor (~215 MB/replay:
// 134 MB compulsory writes + ~81 MB reads after free cross-replay L2 hits),
// so only DRAM efficiency is left. 128-thread blocks for fine-grained
// per-SM block packing at ~90 regs.

#define RD_W  512
#define RD_HW (512 * 512)
#define RPT   4

__global__ __launch_bounds__(128) void react_diff_kernel(
    const float* __restrict__ x,
    const float* __restrict__ params,
    float* __restrict__ out)
{
    const float inv_dx2 = 1.0f / (0.06451612903f * 0.06451612903f); // 240.25

    int t    = blockIdx.x * blockDim.x + threadIdx.x; // 0 .. 2^19-1
    int xg   = t & 63;            // 8-float group within row (512/8 = 64)
    int tile = (t >> 6) & 127;    // 4-row tile index (512/4 = 128)
    int b    = t >> 13;           // batch
    int lane = threadIdx.x & 31;

    const float* Ubase = x + (size_t)b * 2 * RD_HW;
    const float* Vbase = Ubase + RD_HW;
    float* OU = out + (size_t)b * 2 * RD_HW;
    float* OV = OU + RD_HW;

    float pa = __ldg(&params[b * 3 + 0]);
    float pb = __ldg(&params[b * 3 + 1]);
    float pk = __ldg(&params[b * 3 + 2]);

    int y0 = tile * RPT;
    int x0 = xg << 3;
    int xl = (x0 - 1) & 511;
    int xr = (x0 + 8) & 511;
    int q0 = xg << 1;       // first float4 index
    int q1 = q0 + 1;        // second float4 index

    #define LD4U(y,q) (((const float4*)(Ubase + (size_t)(y) * RD_W))[q])
    #define LD4V(y,q) (((const float4*)(Vbase + (size_t)(y) * RD_W))[q])

    int ym1 = (y0 - 1) & 511;
    float4 Uu0 = LD4U(ym1, q0), Uu1 = LD4U(ym1, q1);
    float4 Uc0 = LD4U(y0,  q0), Uc1 = LD4U(y0,  q1);
    float4 Un0 = LD4U(y0+1,q0), Un1 = LD4U(y0+1,q1);
    float4 Vu0 = LD4V(ym1, q0), Vu1 = LD4V(ym1, q1);
    float4 Vc0 = LD4V(y0,  q0), Vc1 = LD4V(y0,  q1);
    float4 Vn0 = LD4V(y0+1,q0), Vn1 = LD4V(y0+1,q1);

    #pragma unroll
    for (int r = 0; r < RPT; r++) {
        int y = y0 + r;
        float4 Ud0 = Un0, Ud1 = Un1;
        float4 Vd0 = Vn0, Vd1 = Vn1;
        if (r < RPT - 1) {            // prefetch down-row of next center
            int yn = (y + 2) & 511;
            Un0 = LD4U(yn, q0); Un1 = LD4U(yn, q1);
            Vn0 = LD4V(yn, q0); Vn1 = LD4V(yn, q1);
        }

        // horizontal neighbors across the 8-float group boundary via shuffle
        float Ul = __shfl_up_sync(0xFFFFFFFFu, Uc1.w, 1);
        float Vl = __shfl_up_sync(0xFFFFFFFFu, Vc1.w, 1);
        float Ur = __shfl_down_sync(0xFFFFFFFFu, Uc0.x, 1);
        float Vr = __shfl_down_sync(0xFFFFFFFFu, Vc0.x, 1);
        if (lane == 0) {
            Ul = Ubase[(size_t)y * RD_W + xl];
            Vl = Vbase[(size_t)y * RD_W + xl];
        }
        if (lane == 31) {
            Ur = Ubase[(size_t)y * RD_W + xr];
            Vr = Vbase[(size_t)y * RD_W + xr];
        }

        float4 lU0, lU1, lV0, lV1;
        lU0.x = (Ul    + Uc0.y + Uu0.x + Ud0.x - 4.0f * Uc0.x) * inv_dx2;
        lU0.y = (Uc0.x + Uc0.z + Uu0.y + Ud0.y - 4.0f * Uc0.y) * inv_dx2;
        lU0.z = (Uc0.y + Uc0.w + Uu0.z + Ud0.z - 4.0f * Uc0.z) * inv_dx2;
        lU0.w = (Uc0.z + Uc1.x + Uu0.w + Ud0.w - 4.0f * Uc0.w) * inv_dx2;
        lU1.x = (Uc0.w + Uc1.y + Uu1.x + Ud1.x - 4.0f * Uc1.x) * inv_dx2;
        lU1.y = (Uc1.x + Uc1.z + Uu1.y + Ud1.y - 4.0f * Uc1.y) * inv_dx2;
        lU1.z = (Uc1.y + Uc1.w + Uu1.z + Ud1.z - 4.0f * Uc1.z) * inv_dx2;
        lU1.w = (Uc1.z + Ur    + Uu1.w + Ud1.w - 4.0f * Uc1.w) * inv_dx2;

        lV0.x = (Vl    + Vc0.y + Vu0.x + Vd0.x - 4.0f * Vc0.x) * inv_dx2;
        lV0.y = (Vc0.x + Vc0.z + Vu0.y + Vd0.y - 4.0f * Vc0.y) * inv_dx2;
        lV0.z = (Vc0.y + Vc0.w + Vu0.z + Vd0.z - 4.0f * Vc0.z) * inv_dx2;
        lV0.w = (Vc0.z + Vc1.x + Vu0.w + Vd0.w - 4.0f * Vc0.w) * inv_dx2;
        lV1.x = (Vc0.w + Vc1.y + Vu1.x + Vd1.x - 4.0f * Vc1.x) * inv_dx2;
        lV1.y = (Vc1.x + Vc1.z + Vu1.y + Vd1.y - 4.0f * Vc1.y) * inv_dx2;
        lV1.z = (Vc1.y + Vc1.w + Vu1.z + Vd1.z - 4.0f * Vc1.z) * inv_dx2;
        lV1.w = (Vc1.z + Vr    + Vu1.w + Vd1.w - 4.0f * Vc1.w) * inv_dx2;

        float4 dU0, dU1, dV0, dV1;
        dU0.x = pa * lU0.x + Uc0.x - Uc0.x * Uc0.x * Uc0.x - pk - Vc0.x;
        dU0.y = pa * lU0.y + Uc0.y - Uc0.y * Uc0.y * Uc0.y - pk - Vc0.y;
        dU0.z = pa * lU0.z + Uc0.z - Uc0.z * Uc0.z * Uc0.z - pk - Vc0.z;
        dU0.w = pa * lU0.w + Uc0.w - Uc0.w * Uc0.w * Uc0.w - pk - Vc0.w;
        dU1.x = pa * lU1.x + Uc1.x - Uc1.x * Uc1.x * Uc1.x - pk - Vc1.x;
        dU1.y = pa * lU1.y + Uc1.y - Uc1.y * Uc1.y * Uc1.y - pk - Vc1.y;
        dU1.z = pa * lU1.z + Uc1.z - Uc1.z * Uc1.z * Uc1.z - pk - Vc1.z;
        dU1.w = pa * lU1.w + Uc1.w - Uc1.w * Uc1.w * Uc1.w - pk - Vc1.w;

        dV0.x = pb * lV0.x + Uc0.x - Vc0.x;
        dV0.y = pb * lV0.y + Uc0.y - Vc0.y;
        dV0.z = pb * lV0.z + Uc0.z - Vc0.z;
        dV0.w = pb * lV0.w + Uc0.w - Vc0.w;
        dV1.x = pb * lV1.x + Uc1.x - Vc1.x;
        dV1.y = pb * lV1.y + Uc1.y - Vc1.y;
        dV1.z = pb * lV1.z + Uc1.z - Vc1.z;
        dV1.w = pb * lV1.w + Uc1.w - Vc1.w;

        float4* ou = (float4*)(OU + (size_t)y * RD_W);
        float4* ov = (float4*)(OV + (size_t)y * RD_W);
        __stcs(ou + q0, dU0);
        __stcs(ou + q1, dU1);
        __stcs(ov + q0, dV0);
        __stcs(ov + q1, dV1);

        // rotate rows
        Uu0 = Uc0; Uu1 = Uc1; Uc0 = Ud0; Uc1 = Ud1;
        Vu0 = Vc0; Vu1 = Vc1; Vc0 = Vd0; Vc1 = Vd1;
    }
    #undef LD4U
    #undef LD4V
}

extern "C" void kernel_launch(void* const* d_in, const int* in_sizes, int n_in,
                              void* d_out, int out_size)
{
    const float* x      = (const float*)d_in[1];
    const float* params = (const float*)d_in[2];
    float* out          = (float*)d_out;

    // 64 batches * 128 row-tiles * 64 x8-groups = 2^19 threads
    const int threads = 128;
    const int blocks  = (64 * 128 * 64) / threads; // 4096
    react_diff_kernel<<<blocks, threads>>>(x, params, out);
}

// round 9
// speedup vs baseline: 1.0478x; 1.0478x over previous
#include <cuda_runtime.h>

// ReactDiffDynamics: per batch b (64), channels U,V of 512x512 fp32 (periodic):
//   dUdt = a*lap(U) + U - U^3 - k - V
//   dVdt = b*lap(V) + U - V
// lap = 5-point periodic stencil / dx^2, dx = 0.06451612903.
//
// R9: R7's RPT=4 row-marching geometry, tuned for occupancy. R8 proved
// chip MLP = occ x per-thread MLP and occupancy is the cheaper factor here
// (occ 26% -> DRAM 64.8%; occ 40% -> 70.5%). Changes vs R7:
//  - no software prefetch (6 live float4s instead of 8; resident warps cover
//    load latency instead of intra-thread prefetch)
//  - __launch_bounds__(256, 5): ptxas targets <=48 regs -> 5 blocks/SM,
//    occ ~60%.

#define RD_W  512
#define RD_HW (512 * 512)
#define RPT   4

__global__ __launch_bounds__(256, 5) void react_diff_kernel(
    const float* __restrict__ x,
    const float* __restrict__ params,
    float* __restrict__ out)
{
    const float inv_dx2 = 1.0f / (0.06451612903f * 0.06451612903f); // 240.25

    int t    = blockIdx.x * blockDim.x + threadIdx.x; // 0 .. 2^20-1
    int xq   = t & 127;           // float4 group within row
    int tile = (t >> 7) & 127;    // 4-row tile index (512/4 = 128)
    int b    = t >> 14;           // batch
    int lane = threadIdx.x & 31;

    const float* Ubase = x + (size_t)b * 2 * RD_HW;
    const float* Vbase = Ubase + RD_HW;
    float* OU = out + (size_t)b * 2 * RD_HW;
    float* OV = OU + RD_HW;

    float pa = __ldg(&params[b * 3 + 0]);
    float pb = __ldg(&params[b * 3 + 1]);
    float pk = __ldg(&params[b * 3 + 2]);

    int y0 = tile * RPT;
    int x0 = xq << 2;
    int xl = (x0 - 1) & 511;
    int xr = (x0 + 4) & 511;

    #define LDU(y) (((const float4*)(Ubase + (size_t)(y) * RD_W))[xq])
    #define LDV(y) (((const float4*)(Vbase + (size_t)(y) * RD_W))[xq])

    float4 Uu = LDU((y0 - 1) & 511);
    float4 Uc = LDU(y0);
    float4 Vu = LDV((y0 - 1) & 511);
    float4 Vc = LDV(y0);

    #pragma unroll
    for (int r = 0; r < RPT; r++) {
        int y = y0 + r;
        int yd = (y + 1) & 511;
        float4 Ud = LDU(yd);
        float4 Vd = LDV(yd);

        // horizontal neighbors via shuffle; warp-edge lanes load scalar
        float Ul = __shfl_up_sync(0xFFFFFFFFu, Uc.w, 1);
        float Vl = __shfl_up_sync(0xFFFFFFFFu, Vc.w, 1);
        float Ur = __shfl_down_sync(0xFFFFFFFFu, Uc.x, 1);
        float Vr = __shfl_down_sync(0xFFFFFFFFu, Vc.x, 1);
        if (lane == 0) {
            Ul = Ubase[(size_t)y * RD_W + xl];
            Vl = Vbase[(size_t)y * RD_W + xl];
        }
        if (lane == 31) {
            Ur = Ubase[(size_t)y * RD_W + xr];
            Vr = Vbase[(size_t)y * RD_W + xr];
        }

        float4 lapU, lapV;
        lapU.x = (Ul   + Uc.y + Uu.x + Ud.x - 4.0f * Uc.x) * inv_dx2;
        lapU.y = (Uc.x + Uc.z + Uu.y + Ud.y - 4.0f * Uc.y) * inv_dx2;
        lapU.z = (Uc.y + Uc.w + Uu.z + Ud.z - 4.0f * Uc.z) * inv_dx2;
        lapU.w = (Uc.z + Ur   + Uu.w + Ud.w - 4.0f * Uc.w) * inv_dx2;

        lapV.x = (Vl   + Vc.y + Vu.x + Vd.x - 4.0f * Vc.x) * inv_dx2;
        lapV.y = (Vc.x + Vc.z + Vu.y + Vd.y - 4.0f * Vc.y) * inv_dx2;
        lapV.z = (Vc.y + Vc.w + Vu.z + Vd.z - 4.0f * Vc.z) * inv_dx2;
        lapV.w = (Vc.z + Vr   + Vu.w + Vd.w - 4.0f * Vc.w) * inv_dx2;

        float4 dU, dV;
        dU.x = pa * lapU.x + Uc.x - Uc.x * Uc.x * Uc.x - pk - Vc.x;
        dU.y = pa * lapU.y + Uc.y - Uc.y * Uc.y * Uc.y - pk - Vc.y;
        dU.z = pa * lapU.z + Uc.z - Uc.z * Uc.z * Uc.z - pk - Vc.z;
        dU.w = pa * lapU.w + Uc.w - Uc.w * Uc.w * Uc.w - pk - Vc.w;

        dV.x = pb * lapV.x + Uc.x - Vc.x;
        dV.y = pb * lapV.y + Uc.y - Vc.y;
        dV.z = pb * lapV.z + Uc.z - Vc.z;
        dV.w = pb * lapV.w + Uc.w - Vc.w;

        __stcs((float4*)(OU + (size_t)y * RD_W) + xq, dU);
        __stcs((float4*)(OV + (size_t)y * RD_W) + xq, dV);

        // rotate rows
        Uu = Uc; Uc = Ud;
        Vu = Vc; Vc = Vd;
    }
    #undef LDU
    #undef LDV
}

extern "C" void kernel_launch(void* const* d_in, const int* in_sizes, int n_in,
                              void* d_out, int out_size)
{
    const float* x      = (const float*)d_in[1];
    const float* params = (const float*)d_in[2];
    float* out          = (float*)d_out;

    // 64 batches * 128 row-tiles * 128 groups = 2^20 threads
    const int threads = 256;
    const int blocks  = (64 * 128 * 128) / threads; // 4096
    react_diff_kernel<<<blocks, threads>>>(x, params, out);
}